// round 15
// baseline (speedup 1.0000x reference)
#include <cuda_runtime.h>
#include <math.h>

// YOLOv1 loss — persistent double-buffered pipeline.
// All previous shapes showed 26-37% DRAM: staging and compute convoyed in
// waves, memory idle during compute. Here 592 persistent CTAs (one wave,
// 4/SM) each loop over ~7 two-sample tiles with two smem buffers: cp.async
// for tile k+1 is in flight while tile k is computed, so memory traffic is
// continuous by construction.
//
// Exactness: max_iou is only ever compared against 0, and union>0 always
// (w,h >= 0.05), so cmask == "exists masked pred box with intersection > 0".
// The intersection arithmetic (cx - 0.5f*w, min/max/sub, >0 test) matches the
// reference ops exactly, so the decision is bit-identical.
//
// Graph-replay invariants: g_partCTA[0..ncta) fully overwritten each run;
// g_count is 0 at every launch start (reset by the last CTA after use).

#define CELLS 49
#define CH 30
#define FPS (CELLS * CH)          // 1470 floats per sample
#define SPT 2                     // samples per tile
#define TILE_F (SPT * FPS * 2)    // 5880 floats per tile (pred+target)
#define TPB 128                   // 4 warps: 0,1 compute; all stage
#define NCTA 592                  // 148 SMs x 4 resident -> single wave
#define MAXB 8192

__device__ __align__(16) float4 g_partCTA[NCTA];
__device__ unsigned int g_count = 0;

__global__ __launch_bounds__(TPB) void yolo_pipe_kernel(
    const float* __restrict__ pred, const float* __restrict__ target,
    float* __restrict__ out, int B, int ntiles, int ncta)
{
    __shared__ __align__(16) float sbuf[2][TILE_F];   // [pred 2940 | target 2940]
    __shared__ int s_list[2][CELLS];
    __shared__ float4 s_red[4];
    __shared__ int s_last;

    const int tid  = threadIdx.x;
    const int lane = tid & 31;
    const int w    = tid >> 5;

    float noobj = 0.f, cls = 0.f, coord = 0.f, objc = 0.f;

    // tiles owned by this CTA: t = blockIdx.x, += ncta
    const int t0 = blockIdx.x;

    // ---- stage one tile into buffer bi (cp.async, or scalar for tails) ----
    auto stage = [&](int t, int bi) {
        const int f0 = t * (SPT * FPS);               // 2940*t floats (16B aligned)
        const int s1 = t * SPT + SPT;                 // one-past-last sample
        float* buf = sbuf[bi];
        if (s1 <= B) {                                // full tile: cp.async 16B
            const float4* gp4 = (const float4*)(pred + f0);
            const float4* gt4 = (const float4*)(target + f0);
            const unsigned bp = (unsigned)__cvta_generic_to_shared(buf);
            const unsigned bt = bp + (SPT * FPS) * 4u;
            const int nv4 = (SPT * FPS) >> 2;         // 735 per tensor
            for (int i = tid; i < nv4; i += TPB) {
                asm volatile("cp.async.cg.shared.global [%0], [%1], 16;\n"
                             :: "r"(bp + 16u * i), "l"(gp4 + i));
                asm volatile("cp.async.cg.shared.global [%0], [%1], 16;\n"
                             :: "r"(bt + 16u * i), "l"(gt4 + i));
            }
        } else {                                      // partial tail tile (B odd)
            const int flen = (B - t * SPT) * FPS;     // floats actually present
            for (int i = tid; i < flen; i += TPB) {
                buf[i] = pred[f0 + i];
                buf[SPT * FPS + i] = target[f0 + i];
            }
        }
        asm volatile("cp.async.commit_group;\n");
    };

    // ---- prologue: prefetch first tile ----
    if (t0 < ntiles) stage(t0, 0);

    for (int t = t0, k = 0; t < ntiles; t += ncta, k++) {
        const int nxt = t + ncta;
        if (nxt < ntiles) {
            stage(nxt, (k + 1) & 1);
            asm volatile("cp.async.wait_group 1;\n" ::: "memory");
        } else {
            asm volatile("cp.async.wait_group 0;\n" ::: "memory");
        }
        __syncthreads();                              // tile t fully in sbuf[k&1]

        // ---- compute tile t: warps 0,1 each own one sample ----
        const int s = t * SPT + w;
        if (w < SPT && s < B) {
            const float* ps = sbuf[k & 1] + w * FPS;
            const float* ts = sbuf[k & 1] + SPT * FPS + w * FPS;

            int nobj = 0;
            #pragma unroll
            for (int half = 0; half < 2; half++) {
                const int c = lane + 32 * half;
                bool isobj = false;
                if (c < CELLS) {
                    const float* pc = ps + c * CH;
                    const float* tc = ts + c * CH;
                    if (tc[4] == 0.f) {               // conf exactly 0/1
                        const float d4 = pc[4] - tc[4];
                        const float d9 = pc[9] - tc[9];
                        noobj += d4 * d4 + d9 * d9;
                    } else {
                        isobj = true;
                        float acc = 0.f;
                        #pragma unroll
                        for (int kk = 10; kk < CH; kk++) {
                            const float d = pc[kk] - tc[kk];
                            acc += d * d;
                        }
                        cls += acc;
                    }
                }
                const unsigned m = __ballot_sync(0xffffffffu, isobj);
                if (isobj)
                    s_list[w][nobj + __popc(m & ((1u << lane) - 1u))] = c;
                nobj += __popc(m);
            }
            __syncwarp();

            const int nbox = 2 * nobj;
            for (int i = lane; i < nbox; i += 32) {
                const int toff = s_list[w][i >> 1] * CH + 5 * (i & 1);
                const float* tb = ts + toff;
                const float tcx = tb[0], tcy = tb[1], tw = tb[2], th = tb[3];
                const float tx0 = tcx - 0.5f * tw, ty0 = tcy - 0.5f * th;
                const float tx1 = tcx + 0.5f * tw, ty1 = tcy + 0.5f * th;

                bool found = false;
                for (int j = 0; j < nbox; j++) {      // j uniform -> LDS broadcast
                    const int po = s_list[w][j >> 1] * CH + 5 * (j & 1);
                    const float pcx = ps[po],     pcy = ps[po + 1];
                    const float pw  = ps[po + 2], ph  = ps[po + 3];
                    const float ix = fminf(pcx + 0.5f * pw, tx1) - fmaxf(pcx - 0.5f * pw, tx0);
                    const float iy = fminf(pcy + 0.5f * ph, ty1) - fmaxf(pcy - 0.5f * ph, ty0);
                    if (ix > 0.f && iy > 0.f && ix * iy > 0.f) { found = true; break; }
                }
                if (found) {
                    const float* pb = ps + toff;
                    const float dx = pb[0] - tcx;
                    const float dy = pb[1] - tcy;
                    const float dw = sqrtf(pb[2]) - sqrtf(tw);
                    const float dh = sqrtf(pb[3]) - sqrtf(th);
                    coord += dx * dx + dy * dy + dw * dw + dh * dh;
                    const float dc = pb[4] - tb[4];
                    objc += dc * dc;
                }
            }
        }
        __syncthreads();            // all reads of sbuf[k&1] done before reuse
    }

    // ---- warp reduce, CTA combine, last-CTA finish ----
    #pragma unroll
    for (int o = 16; o > 0; o >>= 1) {
        noobj += __shfl_down_sync(0xffffffffu, noobj, o);
        cls   += __shfl_down_sync(0xffffffffu, cls, o);
        coord += __shfl_down_sync(0xffffffffu, coord, o);
        objc  += __shfl_down_sync(0xffffffffu, objc, o);
    }
    if (lane == 0)
        s_red[w] = make_float4(noobj, cls, coord, objc);
    __syncthreads();

    if (tid == 0) {
        float4 r = s_red[0];
        #pragma unroll
        for (int k = 1; k < 4; k++) {
            r.x += s_red[k].x; r.y += s_red[k].y;
            r.z += s_red[k].z; r.w += s_red[k].w;
        }
        g_partCTA[blockIdx.x] = r;
        __threadfence();
        const unsigned int old = atomicAdd(&g_count, 1u);
        s_last = (old == (unsigned int)(ncta - 1)) ? 1 : 0;
    }
    __syncthreads();

    if (!s_last) return;

    double a0 = 0.0, a1 = 0.0, a2 = 0.0, a3 = 0.0;
    for (int i = tid; i < ncta; i += TPB) {
        const float4 v = g_partCTA[i];
        a0 += (double)v.x;
        a1 += (double)v.y;
        a2 += (double)v.z;
        a3 += (double)v.w;
    }
    #pragma unroll
    for (int o = 16; o > 0; o >>= 1) {
        a0 += __shfl_down_sync(0xffffffffu, a0, o);
        a1 += __shfl_down_sync(0xffffffffu, a1, o);
        a2 += __shfl_down_sync(0xffffffffu, a2, o);
        a3 += __shfl_down_sync(0xffffffffu, a3, o);
    }
    __shared__ double sd[4][4];
    if (lane == 0) { sd[0][w] = a0; sd[1][w] = a1; sd[2][w] = a2; sd[3][w] = a3; }
    __syncthreads();
    if (tid == 0) {
        double r0 = 0, r1 = 0, r2 = 0, r3 = 0;
        #pragma unroll
        for (int k = 0; k < 4; k++) {
            r0 += sd[0][k]; r1 += sd[1][k]; r2 += sd[2][k]; r3 += sd[3][k];
        }
        const double inv = 1.0 / (double)B;
        const double cls_l = r1 * inv;
        const double obj_l = (r3 + 0.5 * r0) * inv;
        const double crd_l = r2 * 5.0 * inv;
        out[0] = (float)(cls_l + obj_l + crd_l);
        out[1] = (float)cls_l;
        out[2] = (float)obj_l;
        out[3] = (float)crd_l;
        g_count = 0u;                                 // restore replay invariant
    }
}

extern "C" void kernel_launch(void* const* d_in, const int* in_sizes, int n_in,
                              void* d_out, int out_size)
{
    const float* pred = (const float*)d_in[0];
    const float* target = (const float*)d_in[1];
    const int B = in_sizes[0] / FPS;
    const int ntiles = (B + SPT - 1) / SPT;
    const int ncta = (ntiles < NCTA) ? ntiles : NCTA;

    yolo_pipe_kernel<<<ncta, TPB>>>(pred, target, (float*)d_out, B, ntiles, ncta);
}